// round 2
// baseline (speedup 1.0000x reference)
#include <cuda_runtime.h>

// Problem constants: B=8, N=4096, D=512
#define BATCH 8
#define NSEQ  4096
#define DD    512
#define MROWS (BATCH * NSEQ)   // 32768

// Scratch (allocation-free rule: __device__ globals)
__device__ float g_Q[MROWS * DD];     // query (normalized in place)
__device__ float g_K[MROWS * DD];     // key   (normalized in place)
__device__ float g_T[MROWS * DD];     // intermediate after GEMM2
__device__ float g_A[MROWS];          // gating scores (pre seq-norm)
__device__ float g_invA[BATCH];       // 1/max(||A[b,:]||, eps)
__device__ float g_G[BATCH * DD];     // pooled vector per batch

// ---------------------------------------------------------------------------
// Tiled fp32 GEMM (NT): C[m,n] = sum_k Aop[m,k] * W[n,k] + bias[n] (+ Q resid)
// BM=128, BN=64, BK=16, 256 threads, 8x4 microtile per thread.
// ASEL: 0 = Aarg (harness input), 1 = g_K, 2 = g_T
// CSEL: 0 = Carg (d_out),        1 = g_Q, 2 = g_K, 3 = g_T
// SCALE: multiply A element [m,k] by g_G[batch(m), k] on load (gk = G * key)
// RES:   epilogue adds g_Q[m,n] (residual)
// ---------------------------------------------------------------------------
constexpr int BM = 128, BN = 64, BK = 16;

template<int ASEL, int CSEL, bool SCALE, bool RES>
__global__ __launch_bounds__(256)
void gemm_nt(const float* __restrict__ Aarg,
             const float* __restrict__ W,
             const float* __restrict__ bias,
             float* __restrict__ Carg)
{
    const float* Ap = (ASEL == 0) ? Aarg : (ASEL == 1) ? g_K : g_T;
    float*       Cp = (CSEL == 0) ? Carg : (CSEL == 1) ? g_Q : (CSEL == 2) ? g_K : g_T;

    __shared__ float As[BK][BM];
    __shared__ float Bs[BK][BN];

    const int m0 = blockIdx.y * BM;
    const int n0 = blockIdx.x * BN;
    const int t  = threadIdx.x;
    const int tx = t & 15;       // 0..15 -> 4 cols each
    const int ty = t >> 4;       // 0..15 -> 8 rows each

    const float* Grow = &g_G[(m0 / NSEQ) * DD];   // whole block is one batch

    float acc[8][4] = {};

    for (int k0 = 0; k0 < DD; k0 += BK) {
        // --- load A tile: 128 rows x 16 cols = 512 float4, 2 per thread ---
        #pragma unroll
        for (int j = 0; j < 2; j++) {
            int idx = t * 2 + j;
            int row = idx >> 2;
            int c4  = idx & 3;
            float4 v = *reinterpret_cast<const float4*>(
                &Ap[(m0 + row) * DD + k0 + c4 * 4]);
            if (SCALE) {
                v.x *= Grow[k0 + c4 * 4 + 0];
                v.y *= Grow[k0 + c4 * 4 + 1];
                v.z *= Grow[k0 + c4 * 4 + 2];
                v.w *= Grow[k0 + c4 * 4 + 3];
            }
            As[c4 * 4 + 0][row] = v.x;
            As[c4 * 4 + 1][row] = v.y;
            As[c4 * 4 + 2][row] = v.z;
            As[c4 * 4 + 3][row] = v.w;
        }
        // --- load W tile: 64 rows x 16 cols = 256 float4, 1 per thread ---
        {
            int row = t >> 2;
            int c4  = t & 3;
            float4 v = *reinterpret_cast<const float4*>(
                &W[(n0 + row) * DD + k0 + c4 * 4]);
            Bs[c4 * 4 + 0][row] = v.x;
            Bs[c4 * 4 + 1][row] = v.y;
            Bs[c4 * 4 + 2][row] = v.z;
            Bs[c4 * 4 + 3][row] = v.w;
        }
        __syncthreads();

        #pragma unroll
        for (int k = 0; k < BK; k++) {
            float4 a0 = *reinterpret_cast<const float4*>(&As[k][ty * 8]);
            float4 a1 = *reinterpret_cast<const float4*>(&As[k][ty * 8 + 4]);
            float4 b0 = *reinterpret_cast<const float4*>(&Bs[k][tx * 4]);
            float ra[8] = {a0.x, a0.y, a0.z, a0.w, a1.x, a1.y, a1.z, a1.w};
            float rb[4] = {b0.x, b0.y, b0.z, b0.w};
            #pragma unroll
            for (int i = 0; i < 8; i++)
                #pragma unroll
                for (int j = 0; j < 4; j++)
                    acc[i][j] = fmaf(ra[i], rb[j], acc[i][j]);
        }
        __syncthreads();
    }

    // --- epilogue: bias (+ residual), vectorized stores ---
    const int cnb = n0 + tx * 4;
    float4 bv = *reinterpret_cast<const float4*>(&bias[cnb]);
    #pragma unroll
    for (int i = 0; i < 8; i++) {
        int cm = m0 + ty * 8 + i;
        float4 v;
        v.x = acc[i][0] + bv.x;
        v.y = acc[i][1] + bv.y;
        v.z = acc[i][2] + bv.z;
        v.w = acc[i][3] + bv.w;
        if (RES) {
            float4 r = *reinterpret_cast<const float4*>(&g_Q[cm * DD + cnb]);
            v.x += r.x; v.y += r.y; v.z += r.z; v.w += r.w;
        }
        *reinterpret_cast<float4*>(&Cp[cm * DD + cnb]) = v;
    }
}

// ---------------------------------------------------------------------------
// Per-row L2 normalize of g_Q and g_K in place. grid = 2*MROWS, block = 128.
// Each thread handles one float4 (512 / 128 = 4 floats).
// ---------------------------------------------------------------------------
__global__ __launch_bounds__(128)
void l2norm_rows()
{
    int rowg = blockIdx.x;
    float* X = (rowg < MROWS) ? g_Q : g_K;
    int r = (rowg < MROWS) ? rowg : rowg - MROWS;

    float4* p = reinterpret_cast<float4*>(&X[r * DD]);
    float4 v = p[threadIdx.x];
    float s = v.x * v.x + v.y * v.y + v.z * v.z + v.w * v.w;

    #pragma unroll
    for (int off = 16; off > 0; off >>= 1)
        s += __shfl_xor_sync(0xFFFFFFFFu, s, off);

    __shared__ float ws[4];
    int lane = threadIdx.x & 31, wid = threadIdx.x >> 5;
    if (lane == 0) ws[wid] = s;
    __syncthreads();
    float tot = ws[0] + ws[1] + ws[2] + ws[3];
    float inv = 1.0f / fmaxf(sqrtf(tot), 1e-12f);

    v.x *= inv; v.y *= inv; v.z *= inv; v.w *= inv;
    p[threadIdx.x] = v;
}

// ---------------------------------------------------------------------------
// Gating scores: g_A[m] = scale * dot(g_Q[m,:], w_g). One warp per row.
// grid = MROWS/8, block = 256 (8 warps).
// ---------------------------------------------------------------------------
__global__ __launch_bounds__(256)
void ascore(const float* __restrict__ wg)
{
    int warp = threadIdx.x >> 5;
    int lane = threadIdx.x & 31;
    int row = blockIdx.x * 8 + warp;

    const float4* q = reinterpret_cast<const float4*>(&g_Q[row * DD]);
    const float4* w = reinterpret_cast<const float4*>(wg);
    float s = 0.0f;
    #pragma unroll
    for (int i = 0; i < 4; i++) {
        float4 a = q[lane + 32 * i];
        float4 b = w[lane + 32 * i];
        s += a.x * b.x + a.y * b.y + a.z * b.z + a.w * b.w;
    }
    #pragma unroll
    for (int off = 16; off > 0; off >>= 1)
        s += __shfl_xor_sync(0xFFFFFFFFu, s, off);

    if (lane == 0)
        g_A[row] = s * 4.419417382415922e-2f;   // 512^-0.5
}

// ---------------------------------------------------------------------------
// Per-batch seq-norm of A: g_invA[b] = 1/max(||A[b,:]||, eps). grid=8, blk=256.
// ---------------------------------------------------------------------------
__global__ __launch_bounds__(256)
void norma()
{
    int b = blockIdx.x, t = threadIdx.x;
    float s = 0.0f;
    for (int i = t; i < NSEQ; i += 256) {
        float v = g_A[b * NSEQ + i];
        s += v * v;
    }
    #pragma unroll
    for (int off = 16; off > 0; off >>= 1)
        s += __shfl_xor_sync(0xFFFFFFFFu, s, off);
    __shared__ float ws[8];
    int lane = t & 31, wid = t >> 5;
    if (lane == 0) ws[wid] = s;
    __syncthreads();
    if (t == 0) {
        float tot = 0.0f;
        #pragma unroll
        for (int i = 0; i < 8; i++) tot += ws[i];
        g_invA[b] = 1.0f / fmaxf(sqrtf(tot), 1e-12f);
    }
}

// ---------------------------------------------------------------------------
// Pooling: g_G[b,d] = invA[b] * sum_n g_A[b,n] * g_Q[b,n,d].
// grid = (8 d-chunks, 8 batches), block = 256 (64 d-lanes x 4 n-stripes).
// ---------------------------------------------------------------------------
__global__ __launch_bounds__(256)
void gpool()
{
    int b = blockIdx.y;
    int chunk = blockIdx.x;
    int tx = threadIdx.x & 63;
    int st = threadIdx.x >> 6;
    int d = chunk * 64 + tx;

    float acc = 0.0f;
    for (int n = st; n < NSEQ; n += 4) {
        acc += g_A[b * NSEQ + n] * g_Q[(b * NSEQ + n) * DD + d];
    }

    __shared__ float sm[4][64];
    sm[st][tx] = acc;
    __syncthreads();
    if (st == 0) {
        float tot = sm[0][tx] + sm[1][tx] + sm[2][tx] + sm[3][tx];
        g_G[b * DD + d] = tot * g_invA[b];
    }
}

// ---------------------------------------------------------------------------
extern "C" void kernel_launch(void* const* d_in, const int* in_sizes, int n_in,
                              void* d_out, int out_size)
{
    const float* a  = (const float*)d_in[0];
    const float* b  = (const float*)d_in[1];
    const float* Wq = (const float*)d_in[2];
    const float* bq = (const float*)d_in[3];
    const float* Wk = (const float*)d_in[4];
    const float* bk = (const float*)d_in[5];
    const float* wg = (const float*)d_in[6];
    const float* Wp = (const float*)d_in[7];
    const float* bp = (const float*)d_in[8];
    const float* Wf = (const float*)d_in[9];
    const float* bf = (const float*)d_in[10];
    float* out = (float*)d_out;

    dim3 gg(DD / BN, MROWS / BM);   // (8, 256)

    // query_u = a @ Wq^T + bq ; key_u = b @ Wk^T + bk
    gemm_nt<0, 1, false, false><<<gg, 256>>>(a, Wq, bq, nullptr);
    gemm_nt<0, 2, false, false><<<gg, 256>>>(b, Wk, bk, nullptr);
    // L2 normalize rows of Q and K in place
    l2norm_rows<<<2 * MROWS, 128>>>();
    // gating scores + per-batch seq norm + pooled G
    ascore<<<MROWS / 8, 256>>>(wg);
    norma<<<BATCH, 256>>>();
    gpool<<<dim3(8, BATCH), 256>>>();
    // T = (G*K) @ Wp^T + bp + Q
    gemm_nt<1, 3, true, true><<<gg, 256>>>(nullptr, Wp, bp, nullptr);
    // out = T @ Wf^T + bf
    gemm_nt<2, 0, false, false><<<gg, 256>>>(nullptr, Wf, bf, out);
}

// round 5
// speedup vs baseline: 1.8805x; 1.8805x over previous
#include <cuda_runtime.h>
#include <cuda_bf16.h>
#include <cstdint>

#define BATCH 8
#define NSEQ  4096
#define DD    512
#define MROWS (BATCH * NSEQ)   // 32768

// Scratch (__device__ globals; allocation-free rule)
__device__ float g_Q[MROWS * DD];
__device__ float g_K[MROWS * DD];
__device__ float g_T[MROWS * DD];
__device__ float g_A[MROWS];
__device__ float g_invA[BATCH];
__device__ float g_G[BATCH * DD];
__device__ float g_Gp[8][BATCH * DD];   // gpool partials (8 n-splits)

// ---------------------------------------------------------------------------
// Tensor-core GEMM (NT): C[m,n] = sum_k Aop[m,k]*W[n,k] + bias[n] (+Q resid)
// fp32 emulated via 3-term bf16 split: Ah*Bh + Ah*Bl + Al*Bh.
// Block tile 128x128x32, 256 threads = 8 warps (4m x 2n), warp tile 32x64.
// mma.sync.aligned.m16n8k16.row.col.f32.bf16.bf16.f32
// Shared layout: per 16-k subtile, rows padded to 24 halves (12 b32 words)
// -> fragment b32 reads at word (12*row + tg) are bank-conflict-free.
// ---------------------------------------------------------------------------
constexpr int BM = 128, BN = 128, BK = 32;
constexpr int SROW = 24;                 // halves per row (16 data + 8 pad)
constexpr int SUB = 128 * SROW;          // halves per 16-k subtile plane

#define MMA_BF16(d, a, b)                                                    \
    asm volatile(                                                            \
        "mma.sync.aligned.m16n8k16.row.col.f32.bf16.bf16.f32 "               \
        "{%0,%1,%2,%3},{%4,%5,%6,%7},{%8,%9},{%0,%1,%2,%3};"                 \
        : "+f"(d[0]), "+f"(d[1]), "+f"(d[2]), "+f"(d[3])                     \
        : "r"(a[0]), "r"(a[1]), "r"(a[2]), "r"(a[3]), "r"(b[0]), "r"(b[1]))

template<int ASEL, int CSEL, bool SCALE, bool RES>
__global__ __launch_bounds__(256, 1)
void gemm_tc(const float* __restrict__ Aarg,
             const float* __restrict__ W,
             const float* __restrict__ bias,
             float* __restrict__ Carg)
{
    const float* Ap = (ASEL == 0) ? Aarg : (ASEL == 1) ? g_K : g_T;
    float*       Cp = (CSEL == 0) ? Carg : (CSEL == 1) ? g_Q : (CSEL == 2) ? g_K : g_T;

    // 4 planes x 2 subtiles x 128 rows x 24 halves = 49152 B (= 48 KB limit)
    __shared__ __nv_bfloat16 sm[4 * 2 * SUB];
    __nv_bfloat16* sAh = sm;
    __nv_bfloat16* sAl = sm + 2 * SUB;
    __nv_bfloat16* sBh = sm + 4 * SUB;
    __nv_bfloat16* sBl = sm + 6 * SUB;

    const int m0 = blockIdx.y * BM;
    const int n0 = blockIdx.x * BN;
    const int t  = threadIdx.x;
    const int lane = t & 31;
    const int w    = t >> 5;
    const int wm = (w >> 1) * 32;   // warp m offset
    const int wn = (w & 1) * 64;    // warp n offset
    const int g  = lane >> 2;       // group id
    const int tg = lane & 3;        // thread-in-group

    const float* Grow = &g_G[(m0 / NSEQ) * DD];

    float c[2][8][4] = {};
    float4 av[4], bv[4];

    const int lrow = t >> 3;        // 0..31
    const int lc4  = t & 7;         // 0..7 -> k base lc4*4

    auto load_stage = [&](int k0) {
        #pragma unroll
        for (int q = 0; q < 4; q++) {
            int row = q * 32 + lrow;
            int kb  = k0 + lc4 * 4;
            float4 va = *reinterpret_cast<const float4*>(&Ap[(m0 + row) * DD + kb]);
            if (SCALE) {
                va.x *= Grow[kb + 0];
                va.y *= Grow[kb + 1];
                va.z *= Grow[kb + 2];
                va.w *= Grow[kb + 3];
            }
            av[q] = va;
            bv[q] = *reinterpret_cast<const float4*>(&W[(n0 + row) * DD + kb]);
        }
    };

    auto split_store = [&](__nv_bfloat16* hi, __nv_bfloat16* lo, const float4& v,
                           int row) {
        int kk   = lc4 >> 2;              // which 16-k subtile
        int kloc = (lc4 & 3) * 4;         // 0,4,8,12
        int base = kk * SUB + row * SROW + kloc;
        float f[4] = {v.x, v.y, v.z, v.w};
        __nv_bfloat16 h[4], l[4];
        #pragma unroll
        for (int i = 0; i < 4; i++) {
            h[i] = __float2bfloat16(f[i]);
            l[i] = __float2bfloat16(f[i] - __bfloat162float(h[i]));
        }
        *reinterpret_cast<__nv_bfloat162*>(&hi[base])     = __nv_bfloat162(h[0], h[1]);
        *reinterpret_cast<__nv_bfloat162*>(&hi[base + 2]) = __nv_bfloat162(h[2], h[3]);
        *reinterpret_cast<__nv_bfloat162*>(&lo[base])     = __nv_bfloat162(l[0], l[1]);
        *reinterpret_cast<__nv_bfloat162*>(&lo[base + 2]) = __nv_bfloat162(l[2], l[3]);
    };

    load_stage(0);

    for (int s = 0; s < DD / BK; s++) {
        #pragma unroll
        for (int q = 0; q < 4; q++) {
            int row = q * 32 + lrow;
            split_store(sAh, sAl, av[q], row);
            split_store(sBh, sBl, bv[q], row);
        }
        __syncthreads();

        if (s + 1 < DD / BK) load_stage((s + 1) * BK);

        #pragma unroll
        for (int kk = 0; kk < 2; kk++) {
            const uint32_t* Awh = reinterpret_cast<const uint32_t*>(sAh + kk * SUB);
            const uint32_t* Awl = reinterpret_cast<const uint32_t*>(sAl + kk * SUB);
            const uint32_t* Bwh = reinterpret_cast<const uint32_t*>(sBh + kk * SUB);
            const uint32_t* Bwl = reinterpret_cast<const uint32_t*>(sBl + kk * SUB);

            uint32_t ah[2][4], al[2][4];
            #pragma unroll
            for (int i = 0; i < 2; i++) {
                int r = wm + i * 16 + g;
                ah[i][0] = Awh[r * 12 + tg];
                ah[i][1] = Awh[(r + 8) * 12 + tg];
                ah[i][2] = Awh[r * 12 + tg + 4];
                ah[i][3] = Awh[(r + 8) * 12 + tg + 4];
                al[i][0] = Awl[r * 12 + tg];
                al[i][1] = Awl[(r + 8) * 12 + tg];
                al[i][2] = Awl[r * 12 + tg + 4];
                al[i][3] = Awl[(r + 8) * 12 + tg + 4];
            }
            uint32_t bh[8][2], bl[8][2];
            #pragma unroll
            for (int j = 0; j < 8; j++) {
                int nb = wn + j * 8 + g;
                bh[j][0] = Bwh[nb * 12 + tg];
                bh[j][1] = Bwh[nb * 12 + tg + 4];
                bl[j][0] = Bwl[nb * 12 + tg];
                bl[j][1] = Bwl[nb * 12 + tg + 4];
            }
            #pragma unroll
            for (int i = 0; i < 2; i++)
                #pragma unroll
                for (int j = 0; j < 8; j++) {
                    MMA_BF16(c[i][j], ah[i], bh[j]);
                    MMA_BF16(c[i][j], ah[i], bl[j]);
                    MMA_BF16(c[i][j], al[i], bh[j]);
                }
        }
        __syncthreads();
    }

    // Epilogue: bias (+ residual), float2 stores
    #pragma unroll
    for (int i = 0; i < 2; i++) {
        #pragma unroll
        for (int j = 0; j < 8; j++) {
            int rm = m0 + wm + i * 16 + g;
            int cn = n0 + wn + j * 8 + 2 * tg;
            float2 bb = *reinterpret_cast<const float2*>(&bias[cn]);
            float2 v0 = make_float2(c[i][j][0] + bb.x, c[i][j][1] + bb.y);
            float2 v1 = make_float2(c[i][j][2] + bb.x, c[i][j][3] + bb.y);
            if (RES) {
                float2 r0 = *reinterpret_cast<const float2*>(&g_Q[rm * DD + cn]);
                float2 r1 = *reinterpret_cast<const float2*>(&g_Q[(rm + 8) * DD + cn]);
                v0.x += r0.x; v0.y += r0.y;
                v1.x += r1.x; v1.y += r1.y;
            }
            *reinterpret_cast<float2*>(&Cp[rm * DD + cn])       = v0;
            *reinterpret_cast<float2*>(&Cp[(rm + 8) * DD + cn]) = v1;
        }
    }
}

// ---------------------------------------------------------------------------
// L2-normalize rows of g_Q and g_K in place; for Q rows also emit the gating
// score g_A[row] = scale * dot(q_norm, w_g). grid = 2*MROWS, block = 128.
// ---------------------------------------------------------------------------
__global__ __launch_bounds__(128)
void l2norm_ascore(const float* __restrict__ wg)
{
    int rowg = blockIdx.x;
    bool isQ = rowg < MROWS;
    float* X = isQ ? g_Q : g_K;
    int r = isQ ? rowg : rowg - MROWS;

    float4* p = reinterpret_cast<float4*>(&X[r * DD]);
    float4 v = p[threadIdx.x];
    float s = v.x * v.x + v.y * v.y + v.z * v.z + v.w * v.w;

    #pragma unroll
    for (int off = 16; off > 0; off >>= 1)
        s += __shfl_xor_sync(0xFFFFFFFFu, s, off);

    __shared__ float ws[4];
    int lane = threadIdx.x & 31, wid = threadIdx.x >> 5;
    if (lane == 0) ws[wid] = s;
    __syncthreads();
    float tot = ws[0] + ws[1] + ws[2] + ws[3];
    float inv = 1.0f / fmaxf(sqrtf(tot), 1e-12f);

    v.x *= inv; v.y *= inv; v.z *= inv; v.w *= inv;
    p[threadIdx.x] = v;

    if (isQ) {
        const float4* wv = reinterpret_cast<const float4*>(wg);
        float4 wq = wv[threadIdx.x];
        float s2 = v.x * wq.x + v.y * wq.y + v.z * wq.z + v.w * wq.w;
        #pragma unroll
        for (int off = 16; off > 0; off >>= 1)
            s2 += __shfl_xor_sync(0xFFFFFFFFu, s2, off);
        __syncthreads();
        if (lane == 0) ws[wid] = s2;
        __syncthreads();
        if (threadIdx.x == 0)
            g_A[r] = (ws[0] + ws[1] + ws[2] + ws[3]) * 4.419417382415922e-2f;
    }
}

// Per-batch seq-norm of A. grid = 8, block = 256.
__global__ __launch_bounds__(256)
void norma()
{
    int b = blockIdx.x, t = threadIdx.x;
    float s = 0.0f;
    for (int i = t; i < NSEQ; i += 256) {
        float v = g_A[b * NSEQ + i];
        s += v * v;
    }
    #pragma unroll
    for (int off = 16; off > 0; off >>= 1)
        s += __shfl_xor_sync(0xFFFFFFFFu, s, off);
    __shared__ float ws[8];
    int lane = t & 31, wid = t >> 5;
    if (lane == 0) ws[wid] = s;
    __syncthreads();
    if (t == 0) {
        float tot = 0.0f;
        #pragma unroll
        for (int i = 0; i < 8; i++) tot += ws[i];
        g_invA[b] = 1.0f / fmaxf(sqrtf(tot), 1e-12f);
    }
}

// Pooling phase 1: partial sums over n-slices. grid=(4 dchunk, 8 batch, 8 nsplit)
__global__ __launch_bounds__(128)
void gpoolp()
{
    int b  = blockIdx.y;
    int d  = blockIdx.x * 128 + threadIdx.x;
    int ns = blockIdx.z;
    int n0 = ns * (NSEQ / 8);

    float acc = 0.0f;
    #pragma unroll 4
    for (int n = n0; n < n0 + NSEQ / 8; n++)
        acc += g_A[b * NSEQ + n] * g_Q[(b * NSEQ + n) * DD + d];
    g_Gp[ns][b * DD + d] = acc;
}

// Pooling phase 2: reduce partials, apply invA. grid = 32, block = 128.
__global__ __launch_bounds__(128)
void gpoolr()
{
    int i = blockIdx.x * 128 + threadIdx.x;
    int b = i / DD;
    float s = 0.0f;
    #pragma unroll
    for (int p = 0; p < 8; p++) s += g_Gp[p][i];
    g_G[i] = s * g_invA[b];
}

// ---------------------------------------------------------------------------
extern "C" void kernel_launch(void* const* d_in, const int* in_sizes, int n_in,
                              void* d_out, int out_size)
{
    const float* a  = (const float*)d_in[0];
    const float* b  = (const float*)d_in[1];
    const float* Wq = (const float*)d_in[2];
    const float* bq = (const float*)d_in[3];
    const float* Wk = (const float*)d_in[4];
    const float* bk = (const float*)d_in[5];
    const float* wg = (const float*)d_in[6];
    const float* Wp = (const float*)d_in[7];
    const float* bp = (const float*)d_in[8];
    const float* Wf = (const float*)d_in[9];
    const float* bf = (const float*)d_in[10];
    float* out = (float*)d_out;

    dim3 gg(DD / BN, MROWS / BM);   // (4, 256)

    gemm_tc<0, 1, false, false><<<gg, 256>>>(a, Wq, bq, nullptr);
    gemm_tc<0, 2, false, false><<<gg, 256>>>(b, Wk, bk, nullptr);
    l2norm_ascore<<<2 * MROWS, 128>>>(wg);
    norma<<<BATCH, 256>>>();
    gpoolp<<<dim3(4, BATCH, 8), 128>>>();
    gpoolr<<<32, 128>>>();
    gemm_tc<1, 3, true, true><<<gg, 256>>>(nullptr, Wp, bp, nullptr);
    gemm_tc<2, 0, false, false><<<gg, 256>>>(nullptr, Wf, bf, out);
}